// round 1
// baseline (speedup 1.0000x reference)
#include <cuda_runtime.h>
#include <cstdint>

// ---------------------------------------------------------------------------
// VQ-VAE forward. Shapes:
//   x (16,768,4096) -> conv1(K4,S2,P1,relu) -> (16,32,2048)
//   -> conv2(K4,S2,P1,relu) -> (16,64,1024) -> conv3(K3,P1) -> res stack
//   -> 1x1 prevq -> VQ(512x64) -> conv3 -> res stack
//   -> convT1(64->32,K4,S2,P1,relu) -> (16,32,2048)
//   -> convT2(32->64,K4,S2,P1) -> (16,64,4096)
// ---------------------------------------------------------------------------

// Scratch (device globals; no allocations allowed)
__device__ float g_h1[(size_t)16 * 32 * 2048];   // conv1 out / 4 MB
__device__ float g_bufA[(size_t)16 * 64 * 1024]; // ping
__device__ float g_bufB[(size_t)16 * 64 * 1024]; // pong
__device__ float g_t1[(size_t)16 * 32 * 2048];   // convT1 out

// ---------------------------------------------------------------------------
// conv1: 768 -> 32, K=4, S=2, P=1, bias, ReLU.  Tile: 128 out positions.
// smem: xs[32][258] + ws[32][4][32]
// ---------------------------------------------------------------------------
__global__ void __launch_bounds__(256) k_conv1(
    const float* __restrict__ x, const float* __restrict__ w,
    const float* __restrict__ bias, float* __restrict__ out)
{
    extern __shared__ float sm[];
    float* xs = sm;               // [32][258]
    float* ws = sm + 32 * 258;    // [32][4][32]
    const int n   = blockIdx.y;
    const int t0  = blockIdx.x * 128;
    const int tid = threadIdx.x;
    const int lane = tid & 31;
    const int ocg  = tid >> 5;    // oc_base = ocg*4
    const int xbase = 2 * t0 - 1;

    float acc[4][4];
#pragma unroll
    for (int r = 0; r < 4; r++)
#pragma unroll
        for (int i = 0; i < 4; i++) acc[r][i] = 0.f;

    for (int c0 = 0; c0 < 768; c0 += 32) {
        __syncthreads();
        for (int idx = tid; idx < 32 * 258; idx += 256) {
            int c = idx / 258, j = idx - c * 258;
            int g = xbase + j;
            float v = 0.f;
            if (g >= 0 && g < 4096) v = x[((size_t)(n * 768 + c0 + c)) * 4096 + g];
            xs[idx] = v;
        }
        for (int idx = tid; idx < 32 * 4 * 32; idx += 256) {
            int c = idx >> 7, rem = idx & 127, k = rem >> 5, o = rem & 31;
            ws[idx] = w[((size_t)o * 768 + c0 + c) * 4 + k];
        }
        __syncthreads();
#pragma unroll 4
        for (int c = 0; c < 32; c++) {
            const float* xr = xs + c * 258;
            const float4* wr = (const float4*)(ws + c * 128);
#pragma unroll
            for (int k = 0; k < 4; k++) {
                float4 wv = wr[k * 8 + ocg];
#pragma unroll
                for (int i = 0; i < 4; i++) {
                    float xv = xr[2 * (lane + 32 * i) + k];
                    acc[0][i] = fmaf(wv.x, xv, acc[0][i]);
                    acc[1][i] = fmaf(wv.y, xv, acc[1][i]);
                    acc[2][i] = fmaf(wv.z, xv, acc[2][i]);
                    acc[3][i] = fmaf(wv.w, xv, acc[3][i]);
                }
            }
        }
    }
#pragma unroll
    for (int r = 0; r < 4; r++) {
        int oc = ocg * 4 + r;
        float bv = bias[oc];
#pragma unroll
        for (int i = 0; i < 4; i++)
            out[((size_t)(n * 32 + oc)) * 2048 + t0 + lane + 32 * i] =
                fmaxf(acc[r][i] + bv, 0.f);
    }
}

// ---------------------------------------------------------------------------
// conv2: 32 -> 64, K=4, S=2, P=1, bias, ReLU. Single channel pass.
// smem: xs[32][258] + ws[32][4][64]
// ---------------------------------------------------------------------------
__global__ void __launch_bounds__(256) k_conv2(
    const float* __restrict__ x, const float* __restrict__ w,
    const float* __restrict__ bias, float* __restrict__ out)
{
    extern __shared__ float sm[];
    float* xs = sm;             // [32][258]
    float* ws = sm + 32 * 258;  // [32][4][64]
    const int n = blockIdx.y;
    const int t0 = blockIdx.x * 128;
    const int tid = threadIdx.x, lane = tid & 31, ocg = tid >> 5;
    const int xbase = 2 * t0 - 1;

    for (int idx = tid; idx < 32 * 258; idx += 256) {
        int c = idx / 258, j = idx - c * 258;
        int g = xbase + j;
        float v = 0.f;
        if (g >= 0 && g < 2048) v = x[((size_t)(n * 32 + c)) * 2048 + g];
        xs[idx] = v;
    }
    for (int idx = tid; idx < 32 * 4 * 64; idx += 256) {
        int c = idx >> 8, rem = idx & 255, k = rem >> 6, o = rem & 63;
        ws[idx] = w[((size_t)o * 32 + c) * 4 + k];
    }
    __syncthreads();

    float acc[8][4];
#pragma unroll
    for (int r = 0; r < 8; r++)
#pragma unroll
        for (int i = 0; i < 4; i++) acc[r][i] = 0.f;

#pragma unroll 4
    for (int c = 0; c < 32; c++) {
        const float* xr = xs + c * 258;
        const float4* wr = (const float4*)(ws + c * 256);
#pragma unroll
        for (int k = 0; k < 4; k++) {
            float4 w0 = wr[k * 16 + ocg * 2];
            float4 w1 = wr[k * 16 + ocg * 2 + 1];
#pragma unroll
            for (int i = 0; i < 4; i++) {
                float xv = xr[2 * (lane + 32 * i) + k];
                acc[0][i] = fmaf(w0.x, xv, acc[0][i]);
                acc[1][i] = fmaf(w0.y, xv, acc[1][i]);
                acc[2][i] = fmaf(w0.z, xv, acc[2][i]);
                acc[3][i] = fmaf(w0.w, xv, acc[3][i]);
                acc[4][i] = fmaf(w1.x, xv, acc[4][i]);
                acc[5][i] = fmaf(w1.y, xv, acc[5][i]);
                acc[6][i] = fmaf(w1.z, xv, acc[6][i]);
                acc[7][i] = fmaf(w1.w, xv, acc[7][i]);
            }
        }
    }
#pragma unroll
    for (int r = 0; r < 8; r++) {
        int oc = ocg * 8 + r;
        float bv = bias[oc];
#pragma unroll
        for (int i = 0; i < 4; i++)
            out[((size_t)(n * 64 + oc)) * 1024 + t0 + lane + 32 * i] =
                fmaxf(acc[r][i] + bv, 0.f);
    }
}

// ---------------------------------------------------------------------------
// Generic 64->64 conv, K in {1,3}, pad=(K-1)/2, bias, optional ReLU. L=1024.
// ---------------------------------------------------------------------------
template <int K, bool RELU>
__global__ void __launch_bounds__(256) k_conv64(
    const float* __restrict__ x, const float* __restrict__ w,
    const float* __restrict__ bias, float* __restrict__ out)
{
    constexpr int PAD = (K - 1) / 2;
    constexpr int XR = 128 + K - 1;
    extern __shared__ float sm[];
    float* xs = sm;             // [64][XR]
    float* ws = sm + 64 * XR;   // [64][K][64]
    const int n = blockIdx.y;
    const int t0 = blockIdx.x * 128;
    const int tid = threadIdx.x, lane = tid & 31, ocg = tid >> 5;

    for (int idx = tid; idx < 64 * XR; idx += 256) {
        int c = idx / XR, j = idx - c * XR;
        int g = t0 - PAD + j;
        float v = 0.f;
        if (g >= 0 && g < 1024) v = x[((size_t)(n * 64 + c)) * 1024 + g];
        xs[idx] = v;
    }
    for (int idx = tid; idx < 64 * K * 64; idx += 256) {
        int o = idx & 63, ck = idx >> 6;
        int k = ck % K, c = ck / K;
        ws[idx] = w[((size_t)o * 64 + c) * K + k];
    }
    __syncthreads();

    float acc[8][4];
#pragma unroll
    for (int r = 0; r < 8; r++)
#pragma unroll
        for (int i = 0; i < 4; i++) acc[r][i] = 0.f;

#pragma unroll 2
    for (int c = 0; c < 64; c++) {
        const float* xr = xs + c * XR;
        const float4* wr = (const float4*)(ws + c * K * 64);
#pragma unroll
        for (int k = 0; k < K; k++) {
            float4 w0 = wr[k * 16 + ocg * 2];
            float4 w1 = wr[k * 16 + ocg * 2 + 1];
#pragma unroll
            for (int i = 0; i < 4; i++) {
                float xv = xr[lane + 32 * i + k];
                acc[0][i] = fmaf(w0.x, xv, acc[0][i]);
                acc[1][i] = fmaf(w0.y, xv, acc[1][i]);
                acc[2][i] = fmaf(w0.z, xv, acc[2][i]);
                acc[3][i] = fmaf(w0.w, xv, acc[3][i]);
                acc[4][i] = fmaf(w1.x, xv, acc[4][i]);
                acc[5][i] = fmaf(w1.y, xv, acc[5][i]);
                acc[6][i] = fmaf(w1.z, xv, acc[6][i]);
                acc[7][i] = fmaf(w1.w, xv, acc[7][i]);
            }
        }
    }
#pragma unroll
    for (int r = 0; r < 8; r++) {
        int oc = ocg * 8 + r;
        float v0 = bias[oc];
#pragma unroll
        for (int i = 0; i < 4; i++) {
            float v = acc[r][i] + v0;
            if (RELU) v = fmaxf(v, 0.f);
            out[((size_t)(n * 64 + oc)) * 1024 + t0 + lane + 32 * i] = v;
        }
    }
}

// ---------------------------------------------------------------------------
// Fused residual block: out = x + w2 @ relu(conv3(relu(x), w1)) [opt. relu]
// ---------------------------------------------------------------------------
template <bool FINAL_RELU>
__global__ void __launch_bounds__(256) k_resblock(
    const float* __restrict__ x, const float* __restrict__ w1,
    const float* __restrict__ w2, float* __restrict__ out)
{
    extern __shared__ float sm[];
    float* xs  = sm;                 // [64][130]
    float* w1s = sm + 64 * 130;      // [64][3][32]
    float* hs  = w1s + 64 * 3 * 32;  // [32][128]
    float* w2s = hs + 32 * 128;      // [32][64]
    const int n = blockIdx.y, t0 = blockIdx.x * 128;
    const int tid = threadIdx.x, lane = tid & 31, ocg = tid >> 5;

    for (int idx = tid; idx < 64 * 130; idx += 256) {
        int c = idx / 130, j = idx - c * 130;
        int g = t0 - 1 + j;
        float v = 0.f;
        if (g >= 0 && g < 1024) v = x[((size_t)(n * 64 + c)) * 1024 + g];
        xs[idx] = v;
    }
    for (int idx = tid; idx < 64 * 3 * 32; idx += 256) {
        int o = idx & 31, ck = idx >> 5;
        int k = ck % 3, c = ck / 3;
        w1s[idx] = w1[((size_t)o * 64 + c) * 3 + k];
    }
    for (int idx = tid; idx < 32 * 64; idx += 256) {
        int o = idx & 63, c = idx >> 6;
        w2s[idx] = w2[(size_t)o * 32 + c];
    }
    __syncthreads();

    // Phase 1: h = relu(conv3(relu(x)))  (32 ch), thread: 4oc x 4t
    {
        float acc[4][4];
#pragma unroll
        for (int r = 0; r < 4; r++)
#pragma unroll
            for (int i = 0; i < 4; i++) acc[r][i] = 0.f;
#pragma unroll 2
        for (int c = 0; c < 64; c++) {
            const float* xr = xs + c * 130;
            const float4* wr = (const float4*)(w1s + c * 96);
#pragma unroll
            for (int k = 0; k < 3; k++) {
                float4 wv = wr[k * 8 + ocg];
#pragma unroll
                for (int i = 0; i < 4; i++) {
                    float xv = fmaxf(xr[lane + 32 * i + k], 0.f);
                    acc[0][i] = fmaf(wv.x, xv, acc[0][i]);
                    acc[1][i] = fmaf(wv.y, xv, acc[1][i]);
                    acc[2][i] = fmaf(wv.z, xv, acc[2][i]);
                    acc[3][i] = fmaf(wv.w, xv, acc[3][i]);
                }
            }
        }
#pragma unroll
        for (int r = 0; r < 4; r++)
#pragma unroll
            for (int i = 0; i < 4; i++)
                hs[(ocg * 4 + r) * 128 + lane + 32 * i] = fmaxf(acc[r][i], 0.f);
    }
    __syncthreads();

    // Phase 2: out = x + w2 @ h, thread: 8oc x 4t
    {
        float acc[8][4];
#pragma unroll
        for (int r = 0; r < 8; r++)
#pragma unroll
            for (int i = 0; i < 4; i++) acc[r][i] = 0.f;
#pragma unroll 4
        for (int c = 0; c < 32; c++) {
            const float* hr = hs + c * 128;
            const float4* wr = (const float4*)(w2s + c * 64);
            float4 w0 = wr[ocg * 2];
            float4 w1v = wr[ocg * 2 + 1];
#pragma unroll
            for (int i = 0; i < 4; i++) {
                float hv = hr[lane + 32 * i];
                acc[0][i] = fmaf(w0.x, hv, acc[0][i]);
                acc[1][i] = fmaf(w0.y, hv, acc[1][i]);
                acc[2][i] = fmaf(w0.z, hv, acc[2][i]);
                acc[3][i] = fmaf(w0.w, hv, acc[3][i]);
                acc[4][i] = fmaf(w1v.x, hv, acc[4][i]);
                acc[5][i] = fmaf(w1v.y, hv, acc[5][i]);
                acc[6][i] = fmaf(w1v.z, hv, acc[6][i]);
                acc[7][i] = fmaf(w1v.w, hv, acc[7][i]);
            }
        }
#pragma unroll
        for (int r = 0; r < 8; r++) {
            int oc = ocg * 8 + r;
#pragma unroll
            for (int i = 0; i < 4; i++) {
                float v = xs[oc * 130 + lane + 32 * i + 1] + acc[r][i];
                if (FINAL_RELU) v = fmaxf(v, 0.f);
                out[((size_t)(n * 64 + oc)) * 1024 + t0 + lane + 32 * i] = v;
            }
        }
    }
}

// ---------------------------------------------------------------------------
// VQ: q[n,:,t] = emb[argmin_j ||z[n,:,t]-e_j||^2].  Whole codebook in smem.
// es rows padded to 68 floats (16B-aligned, breaks gather bank conflicts).
// ---------------------------------------------------------------------------
__global__ void __launch_bounds__(128) k_vq(
    const float* __restrict__ z, const float* __restrict__ emb,
    float* __restrict__ q)
{
    extern __shared__ float sm[];
    float* es = sm;             // [512][68]
    float* ns = sm + 512 * 68;  // [512]
    const int tid = threadIdx.x;

    for (int idx = tid; idx < 512 * 64; idx += 128) {
        int j = idx >> 6, c = idx & 63;
        es[j * 68 + c] = emb[idx];
    }
    __syncthreads();
    for (int j = tid; j < 512; j += 128) {
        const float* er = es + j * 68;
        float s = 0.f;
#pragma unroll 8
        for (int c = 0; c < 64; c++) { float v = er[c]; s = fmaf(v, v, s); }
        ns[j] = s;
    }
    __syncthreads();

    const int pos = blockIdx.x * 128 + tid;
    const int n = pos >> 10, t = pos & 1023;

    float zv[64];
#pragma unroll
    for (int c = 0; c < 64; c++) zv[c] = z[((size_t)(n * 64 + c)) * 1024 + t];

    float bestd = 3.4e38f;
    int best = 0;
    for (int j = 0; j < 512; j++) {
        const float4* er = (const float4*)(es + j * 68);
        float dacc[4] = {0.f, 0.f, 0.f, 0.f};
#pragma unroll
        for (int c4 = 0; c4 < 16; c4++) {
            float4 e = er[c4];
            float d = dacc[c4 & 3];
            d = fmaf(zv[4 * c4 + 0], e.x, d);
            d = fmaf(zv[4 * c4 + 1], e.y, d);
            d = fmaf(zv[4 * c4 + 2], e.z, d);
            d = fmaf(zv[4 * c4 + 3], e.w, d);
            dacc[c4 & 3] = d;
        }
        float dist = ns[j] - 2.f * ((dacc[0] + dacc[1]) + (dacc[2] + dacc[3]));
        if (dist < bestd) { bestd = dist; best = j; }
    }
    const float* eb = es + best * 68;
#pragma unroll
    for (int c = 0; c < 64; c++)
        q[((size_t)(n * 64 + c)) * 1024 + t] = eb[c];
}

// ---------------------------------------------------------------------------
// ConvTranspose1d 64->32, K=4, S=2, P=1, bias, ReLU. out (16,32,2048).
// Two taps per output position; tap parity fixed per lane.
// ---------------------------------------------------------------------------
__global__ void __launch_bounds__(256) k_dect1(
    const float* __restrict__ x, const float* __restrict__ w,
    const float* __restrict__ bias, float* __restrict__ out)
{
    extern __shared__ float sm[];
    float* xs = sm;             // [64][130]
    float* ws = sm + 64 * 130;  // [64][4][32]
    const int n = blockIdx.y;
    const int p0 = blockIdx.x * 256;
    const int t0in = (p0 >> 1) - 1;
    const int tid = threadIdx.x, lane = tid & 31, ocg = tid >> 5;

    for (int idx = tid; idx < 64 * 130; idx += 256) {
        int c = idx / 130, j = idx - c * 130;
        int g = t0in + j;
        float v = 0.f;
        if (g >= 0 && g < 1024) v = x[((size_t)(n * 64 + c)) * 1024 + g];
        xs[idx] = v;
    }
    for (int idx = tid; idx < 64 * 4 * 32; idx += 256) {
        int o = idx & 31, ck = idx >> 5;
        int k = ck & 3, c = ck >> 2;
        ws[idx] = w[((size_t)c * 32 + o) * 4 + k];
    }
    __syncthreads();

    const int par = lane & 1;            // p parity (p0 even)
    const int ka = 1 - par, kb = ka + 2;
    const int ja0 = ((lane + 1 - ka) >> 1) + 1;

    float acc[4][8];
#pragma unroll
    for (int r = 0; r < 4; r++)
#pragma unroll
        for (int i = 0; i < 8; i++) acc[r][i] = 0.f;

#pragma unroll 2
    for (int c = 0; c < 64; c++) {
        const float* xr = xs + c * 130;
        const float4* wr = (const float4*)(ws + c * 128);
        float4 wa = wr[ka * 8 + ocg];
        float4 wb = wr[kb * 8 + ocg];
#pragma unroll
        for (int i = 0; i < 8; i++) {
            float xa = xr[ja0 + 16 * i];
            float xb = xr[ja0 + 16 * i - 1];
            acc[0][i] = fmaf(wa.x, xa, acc[0][i]);
            acc[1][i] = fmaf(wa.y, xa, acc[1][i]);
            acc[2][i] = fmaf(wa.z, xa, acc[2][i]);
            acc[3][i] = fmaf(wa.w, xa, acc[3][i]);
            acc[0][i] = fmaf(wb.x, xb, acc[0][i]);
            acc[1][i] = fmaf(wb.y, xb, acc[1][i]);
            acc[2][i] = fmaf(wb.z, xb, acc[2][i]);
            acc[3][i] = fmaf(wb.w, xb, acc[3][i]);
        }
    }
#pragma unroll
    for (int r = 0; r < 4; r++) {
        int oc = ocg * 4 + r;
        float bv = bias[oc];
#pragma unroll
        for (int i = 0; i < 8; i++)
            out[((size_t)(n * 32 + oc)) * 2048 + p0 + lane + 32 * i] =
                fmaxf(acc[r][i] + bv, 0.f);
    }
}

// ---------------------------------------------------------------------------
// ConvTranspose1d 32->64, K=4, S=2, P=1, bias. out (16,64,4096) = final.
// ---------------------------------------------------------------------------
__global__ void __launch_bounds__(256) k_dect2(
    const float* __restrict__ x, const float* __restrict__ w,
    const float* __restrict__ bias, float* __restrict__ out)
{
    extern __shared__ float sm[];
    float* xs = sm;             // [32][130]
    float* ws = sm + 32 * 130;  // [32][4][64]
    const int n = blockIdx.y;
    const int p0 = blockIdx.x * 256;
    const int t0in = (p0 >> 1) - 1;
    const int tid = threadIdx.x, lane = tid & 31, ocg = tid >> 5;

    for (int idx = tid; idx < 32 * 130; idx += 256) {
        int c = idx / 130, j = idx - c * 130;
        int g = t0in + j;
        float v = 0.f;
        if (g >= 0 && g < 2048) v = x[((size_t)(n * 32 + c)) * 2048 + g];
        xs[idx] = v;
    }
    for (int idx = tid; idx < 32 * 4 * 64; idx += 256) {
        int o = idx & 63, ck = idx >> 6;
        int k = ck & 3, c = ck >> 2;
        ws[idx] = w[((size_t)c * 64 + o) * 4 + k];
    }
    __syncthreads();

    const int par = lane & 1;
    const int ka = 1 - par, kb = ka + 2;
    const int ja0 = ((lane + 1 - ka) >> 1) + 1;

    float acc[8][8];
#pragma unroll
    for (int r = 0; r < 8; r++)
#pragma unroll
        for (int i = 0; i < 8; i++) acc[r][i] = 0.f;

#pragma unroll 2
    for (int c = 0; c < 32; c++) {
        const float* xr = xs + c * 130;
        const float4* wr = (const float4*)(ws + c * 256);
        float4 wa0 = wr[ka * 16 + ocg * 2];
        float4 wa1 = wr[ka * 16 + ocg * 2 + 1];
        float4 wb0 = wr[kb * 16 + ocg * 2];
        float4 wb1 = wr[kb * 16 + ocg * 2 + 1];
#pragma unroll
        for (int i = 0; i < 8; i++) {
            float xa = xr[ja0 + 16 * i];
            float xb = xr[ja0 + 16 * i - 1];
            acc[0][i] = fmaf(wa0.x, xa, acc[0][i]);
            acc[1][i] = fmaf(wa0.y, xa, acc[1][i]);
            acc[2][i] = fmaf(wa0.z, xa, acc[2][i]);
            acc[3][i] = fmaf(wa0.w, xa, acc[3][i]);
            acc[4][i] = fmaf(wa1.x, xa, acc[4][i]);
            acc[5][i] = fmaf(wa1.y, xa, acc[5][i]);
            acc[6][i] = fmaf(wa1.z, xa, acc[6][i]);
            acc[7][i] = fmaf(wa1.w, xa, acc[7][i]);
            acc[0][i] = fmaf(wb0.x, xb, acc[0][i]);
            acc[1][i] = fmaf(wb0.y, xb, acc[1][i]);
            acc[2][i] = fmaf(wb0.z, xb, acc[2][i]);
            acc[3][i] = fmaf(wb0.w, xb, acc[3][i]);
            acc[4][i] = fmaf(wb1.x, xb, acc[4][i]);
            acc[5][i] = fmaf(wb1.y, xb, acc[5][i]);
            acc[6][i] = fmaf(wb1.z, xb, acc[6][i]);
            acc[7][i] = fmaf(wb1.w, xb, acc[7][i]);
        }
    }
#pragma unroll
    for (int r = 0; r < 8; r++) {
        int oc = ocg * 8 + r;
        float bv = bias[oc];
#pragma unroll
        for (int i = 0; i < 8; i++)
            out[((size_t)(n * 64 + oc)) * 4096 + p0 + lane + 32 * i] =
                acc[r][i] + bv;
    }
}

// ---------------------------------------------------------------------------
// Host orchestration
// ---------------------------------------------------------------------------
static const int SM_CONV1 = (32 * 258 + 32 * 4 * 32) * 4;        // 49408
static const int SM_CONV2 = (32 * 258 + 32 * 4 * 64) * 4;        // 65792
static const int SM_C3    = (64 * 130 + 64 * 3 * 64) * 4;        // 82432
static const int SM_C1    = (64 * 128 + 64 * 1 * 64) * 4;        // 49152
static const int SM_RES   = (64 * 130 + 64 * 3 * 32 + 32 * 128 + 32 * 64) * 4; // 82432
static const int SM_VQ    = (512 * 68 + 512) * 4;                // 141312
static const int SM_DT1   = (64 * 130 + 64 * 4 * 32) * 4;        // 66048
static const int SM_DT2   = (32 * 130 + 32 * 4 * 64) * 4;        // 49408

extern "C" void kernel_launch(void* const* d_in, const int* in_sizes, int n_in,
                              void* d_out, int out_size)
{
    (void)in_sizes; (void)n_in; (void)out_size;
    const float* x      = (const float*)d_in[0];
    const float* enc_w1 = (const float*)d_in[1];
    const float* enc_b1 = (const float*)d_in[2];
    const float* enc_w2 = (const float*)d_in[3];
    const float* enc_b2 = (const float*)d_in[4];
    const float* enc_w3 = (const float*)d_in[5];
    const float* enc_b3 = (const float*)d_in[6];
    const float* r0w1   = (const float*)d_in[7];
    const float* r0w2   = (const float*)d_in[8];
    const float* r1w1   = (const float*)d_in[9];
    const float* r1w2   = (const float*)d_in[10];
    const float* pvq_w  = (const float*)d_in[11];
    const float* pvq_b  = (const float*)d_in[12];
    const float* emb    = (const float*)d_in[13];
    const float* dw1    = (const float*)d_in[14];
    const float* db1    = (const float*)d_in[15];
    const float* dr0w1  = (const float*)d_in[16];
    const float* dr0w2  = (const float*)d_in[17];
    const float* dr1w1  = (const float*)d_in[18];
    const float* dr1w2  = (const float*)d_in[19];
    const float* dt1w   = (const float*)d_in[20];
    const float* dt1b   = (const float*)d_in[21];
    const float* dt2w   = (const float*)d_in[22];
    const float* dt2b   = (const float*)d_in[23];
    float* out = (float*)d_out;

    float *h1, *A, *Bb, *t1;
    cudaGetSymbolAddress((void**)&h1, g_h1);
    cudaGetSymbolAddress((void**)&A, g_bufA);
    cudaGetSymbolAddress((void**)&Bb, g_bufB);
    cudaGetSymbolAddress((void**)&t1, g_t1);

    cudaFuncSetAttribute(k_conv1, cudaFuncAttributeMaxDynamicSharedMemorySize, SM_CONV1);
    cudaFuncSetAttribute(k_conv2, cudaFuncAttributeMaxDynamicSharedMemorySize, SM_CONV2);
    cudaFuncSetAttribute(k_conv64<3, false>, cudaFuncAttributeMaxDynamicSharedMemorySize, SM_C3);
    cudaFuncSetAttribute(k_conv64<1, false>, cudaFuncAttributeMaxDynamicSharedMemorySize, SM_C1);
    cudaFuncSetAttribute(k_resblock<false>, cudaFuncAttributeMaxDynamicSharedMemorySize, SM_RES);
    cudaFuncSetAttribute(k_resblock<true>, cudaFuncAttributeMaxDynamicSharedMemorySize, SM_RES);
    cudaFuncSetAttribute(k_vq, cudaFuncAttributeMaxDynamicSharedMemorySize, SM_VQ);
    cudaFuncSetAttribute(k_dect1, cudaFuncAttributeMaxDynamicSharedMemorySize, SM_DT1);
    cudaFuncSetAttribute(k_dect2, cudaFuncAttributeMaxDynamicSharedMemorySize, SM_DT2);

    // Encoder
    k_conv1<<<dim3(16, 16), 256, SM_CONV1>>>(x, enc_w1, enc_b1, h1);
    k_conv2<<<dim3(8, 16), 256, SM_CONV2>>>(h1, enc_w2, enc_b2, A);
    k_conv64<3, false><<<dim3(8, 16), 256, SM_C3>>>(A, enc_w3, enc_b3, Bb);
    k_resblock<false><<<dim3(8, 16), 256, SM_RES>>>(Bb, r0w1, r0w2, A);
    k_resblock<true><<<dim3(8, 16), 256, SM_RES>>>(A, r1w1, r1w2, Bb);
    // pre-VQ 1x1 -> z
    k_conv64<1, false><<<dim3(8, 16), 256, SM_C1>>>(Bb, pvq_w, pvq_b, A);
    // VQ -> q
    k_vq<<<128, 128, SM_VQ>>>(A, emb, Bb);
    // Decoder
    k_conv64<3, false><<<dim3(8, 16), 256, SM_C3>>>(Bb, dw1, db1, A);
    k_resblock<false><<<dim3(8, 16), 256, SM_RES>>>(A, dr0w1, dr0w2, Bb);
    k_resblock<true><<<dim3(8, 16), 256, SM_RES>>>(Bb, dr1w1, dr1w2, A);
    k_dect1<<<dim3(8, 16), 256, SM_DT1>>>(A, dt1w, dt1b, t1);
    k_dect2<<<dim3(16, 16), 256, SM_DT2>>>(t1, dt2w, dt2b, out);
}